// round 9
// baseline (speedup 1.0000x reference)
#include <cuda_runtime.h>
#include <math.h>
#include <stdint.h>

// ---------------------------------------------------------------------------
// Problem constants
// ---------------------------------------------------------------------------
namespace {
constexpr int B_  = 2;
constexpr int N_  = 512;
constexpr int D_  = 128;   // DIM
constexpr int PH_ = 64;    // POS_HID
constexpr int AH_ = 512;   // ATTN_HID
constexpr int K_  = 16;    // K_NEIGH
constexpr int M1  = B_ * N_;    // 1024
constexpr int M2  = M1 * K_;    // 16384
constexpr int NC_ = AH_ + D_;   // 640
}

// ---------------------------------------------------------------------------
// Scratch
// ---------------------------------------------------------------------------
__device__ float g_qkv[M1 * 3 * D_];
__device__ int   g_idx[M1 * K_];
__device__ float g_hid[M2 * PH_];
__device__ float g_QK [2 * M1 * AH_];   // rows 0..1023 = q@aw1, 1024..2047 = k@aw1
__device__ float g_Wc [PH_ * NC_];      // [pw2@aw1 | pw2]
__device__ float g_bc [NC_];            // [pb2@aw1 + ab1 | pb2]
__device__ float g_PE [M2 * D_];
__device__ float g_A  [M2 * AH_];
__device__ float g_SIM[M2 * D_];

// ---------------------------------------------------------------------------
// 1) setup: fused qkv + knn + hid.  One block per query m (1024 blocks, 128 thr).
//    Warp 0 runs the exact R3 KNN; warps 1-3 compute the 384 qkv outputs.
//    Then all threads compute hid for this query's 16 neighbors.
// ---------------------------------------------------------------------------
__global__ __launch_bounds__(128)
void setup_kernel(const float* __restrict__ x, const float* __restrict__ pos,
                  const float* __restrict__ wqkv,
                  const float* __restrict__ pw1, const float* __restrict__ pb1) {
    __shared__ float spx[N_], spy[N_], spz[N_];
    __shared__ float sxx[D_];
    __shared__ int   s_idx[K_];

    const int m = blockIdx.x;
    const int b = m >> 9;
    const int i = m & (N_ - 1);
    const int tid = threadIdx.x;

    for (int t = tid; t < N_; t += 128) {
        const float* p = pos + (size_t)(b * N_ + t) * 3;
        spx[t] = p[0]; spy[t] = p[1]; spz[t] = p[2];
    }
    sxx[tid] = x[b * D_ * N_ + tid * N_ + i];
    __syncthreads();

    if (tid < 32) {
        // ---- KNN (identical arithmetic to the proven R3 kernel) ----
        const int lane = tid;
        const float px = spx[i], py = spy[i], pz = spz[i];
        float d2[16];
#pragma unroll
        for (int t = 0; t < 16; ++t) {
            const int j = lane + 32 * t;
            const float dx = px - spx[j], dy = py - spy[j], dz = pz - spz[j];
            d2[t] = dx * dx + dy * dy + dz * dz;
        }
        unsigned taken = 0u;
        for (int it = 0; it < K_; ++it) {
            float best = 3.4e38f;
            int bt = -1;
#pragma unroll
            for (int t = 0; t < 16; ++t) {
                if (!((taken >> t) & 1u) && d2[t] < best) { best = d2[t]; bt = t; }
            }
            int bj = (bt < 0) ? 0x7fffffff : (lane + 32 * bt);
#pragma unroll
            for (int off = 16; off; off >>= 1) {
                const float ov = __shfl_xor_sync(0xffffffffu, best, off);
                const int   oj = __shfl_xor_sync(0xffffffffu, bj,   off);
                if (ov < best || (ov == best && oj < bj)) { best = ov; bj = oj; }
            }
            if ((bj & 31) == lane) taken |= 1u << (bj >> 5);
            if (lane == 0) { s_idx[it] = bj; g_idx[m * K_ + it] = bj; }
        }
    } else {
        // ---- qkv: 384 outputs over 96 threads (4 each) ----
        const int t0 = tid - 32;
#pragma unroll
        for (int u = 0; u < 4; ++u) {
            const int c = t0 + u * 96;
            float a = 0.f;
#pragma unroll 8
            for (int d = 0; d < D_; ++d) a = fmaf(sxx[d], wqkv[d * 384 + c], a);
            g_qkv[(size_t)m * 384 + c] = a;
        }
    }
    __syncthreads();

    // ---- hid for this query's 16 neighbors ----
    const int h = tid & 63;
    const float w0 = pw1[h], w1 = pw1[64 + h], w2 = pw1[128 + h], bb = pb1[h];
    const float px = spx[i], py = spy[i], pz = spz[i];
#pragma unroll
    for (int kp = 0; kp < 8; ++kp) {
        const int kk = kp * 2 + (tid >> 6);
        const int j = s_idx[kk];
        const float rx = px - spx[j], ry = py - spy[j], rz = pz - spz[j];
        float v = fmaf(rx, w0, fmaf(ry, w1, fmaf(rz, w2, bb)));
        g_hid[(size_t)(m * K_ + kk) * PH_ + h] = fmaxf(v, 0.f);
    }
}

// ---------------------------------------------------------------------------
// 2) prep_w: Wc = [pw2@aw1 | pw2],  bc = [pb2@aw1 + ab1 | pb2]
//    Split-K (4-way) + block reduce for the 64x512 product; 547 blocks.
// ---------------------------------------------------------------------------
__global__ __launch_bounds__(256)
void prep_w_kernel(const float* __restrict__ pw2, const float* __restrict__ pb2,
                   const float* __restrict__ aw1, const float* __restrict__ ab1) {
    const int blk = blockIdx.x;
    const int tid = threadIdx.x;
    if (blk < 512) {
        // W1c = pw2 @ aw1 : 64 outputs per block, 4 K-splits of 32
        const int o = blk * 64 + (tid & 63);
        const int h = o >> 9, c = o & (AH_ - 1);
        const int sp = tid >> 6;
        float s = 0.f;
#pragma unroll
        for (int u = 0; u < 32; ++u) {
            const int d = sp * 32 + u;
            s = fmaf(pw2[h * D_ + d], aw1[d * AH_ + c], s);
        }
        __shared__ float red[4][64];
        red[sp][tid & 63] = s;
        __syncthreads();
        if (tid < 64)
            g_Wc[h * NC_ + c] = red[0][tid] + red[1][tid] + red[2][tid] + red[3][tid];
    } else if (blk < 544) {
        // copy pw2 into cols 512..639
        const int u = (blk - 512) * 256 + tid;
        const int h = u >> 7, d = u & (D_ - 1);
        g_Wc[h * NC_ + AH_ + d] = pw2[h * D_ + d];
    } else {
        const int c = (blk - 544) * 256 + tid;
        if (c < AH_) {
            float s0 = ab1[c], s1 = 0.f;
#pragma unroll 16
            for (int d = 0; d < D_; d += 2) {
                s0 = fmaf(pb2[d],     aw1[d * AH_ + c],       s0);
                s1 = fmaf(pb2[d + 1], aw1[(d + 1) * AH_ + c], s1);
            }
            g_bc[c] = s0 + s1;
        } else if (c < NC_) {
            g_bc[c] = pb2[c - AH_];
        }
    }
}

// ---------------------------------------------------------------------------
// Tensor-core tf32 GEMM (R3 layout, double-buffered). BM = MTW*32.
//   MODE 0 = plain            MODE 1 = A rows gathered from g_qkv (q then k)
//   MODE 2 = AP: cols <512 -> g_A with QA-KA gather + relu; cols >=512 -> g_PE
// ---------------------------------------------------------------------------
__device__ __forceinline__ uint32_t f2tf32(float f) {
    uint32_t u;
    asm("cvt.rna.tf32.f32 %0, %1;" : "=r"(u) : "f"(f));
    return u;
}

__device__ __forceinline__ void mma_tf32(float c[4],
                                         uint32_t a0, uint32_t a1, uint32_t a2, uint32_t a3,
                                         uint32_t b0, uint32_t b1) {
    asm volatile(
        "mma.sync.aligned.m16n8k8.row.col.f32.tf32.tf32.f32 "
        "{%0,%1,%2,%3}, {%4,%5,%6,%7}, {%8,%9}, {%0,%1,%2,%3};"
        : "+f"(c[0]), "+f"(c[1]), "+f"(c[2]), "+f"(c[3])
        : "r"(a0), "r"(a1), "r"(a2), "r"(a3), "r"(b0), "r"(b1));
}

template <int MTW, int MODE, bool HASBIAS>
__global__ __launch_bounds__(256)
void tc_gemm(const float* __restrict__ A, const float* __restrict__ W,
             const float* __restrict__ bias, float* __restrict__ C,
             float* __restrict__ C2, int M, int N, int K) {
    constexpr int BM = MTW * 32;
    __shared__ uint32_t As[2][BM][36];
    __shared__ uint32_t Bs[2][32][136];

    const int tid  = threadIdx.x;
    const int lane = tid & 31;
    const int warp = tid >> 5;
    const int wm = (warp >> 2) * (MTW * 16);
    const int wn = (warp & 3) * 32;
    const int m0 = blockIdx.y * BM;
    const int n0 = blockIdx.x * 128;

    float acc[MTW][4][4];
#pragma unroll
    for (int mi = 0; mi < MTW; ++mi)
#pragma unroll
        for (int ni = 0; ni < 4; ++ni)
#pragma unroll
            for (int e = 0; e < 4; ++e) acc[mi][ni][e] = 0.f;

    auto stage = [&](int k0, int buf) {
#pragma unroll
        for (int t = 0; t < BM / 32; ++t) {
            const int idx = tid + t * 256;
            const int r = idx >> 3, c = (idx & 7) << 2;
            float4 v;
            if (MODE == 1) {
                const int qrow = m0 + r;
                const size_t base = (size_t)(qrow & (M1 - 1)) * 384 + ((qrow >> 10) << 7);
                v = *(const float4*)(A + base + k0 + c);
            } else {
                v = *(const float4*)(A + (size_t)(m0 + r) * K + k0 + c);
            }
            As[buf][r][c + 0] = f2tf32(v.x); As[buf][r][c + 1] = f2tf32(v.y);
            As[buf][r][c + 2] = f2tf32(v.z); As[buf][r][c + 3] = f2tf32(v.w);
        }
#pragma unroll
        for (int t = 0; t < 4; ++t) {
            const int idx = tid + t * 256;
            const int kr = idx >> 5, nc = (idx & 31) << 2;
            const float4 v = *(const float4*)(W + (size_t)(k0 + kr) * N + n0 + nc);
            Bs[buf][kr][nc + 0] = f2tf32(v.x); Bs[buf][kr][nc + 1] = f2tf32(v.y);
            Bs[buf][kr][nc + 2] = f2tf32(v.z); Bs[buf][kr][nc + 3] = f2tf32(v.w);
        }
    };

    auto mmatile = [&](int buf) {
#pragma unroll
        for (int ks = 0; ks < 4; ++ks) {
            const int kk = ks * 8;
            uint32_t af[MTW][4], bf[4][2];
#pragma unroll
            for (int mi = 0; mi < MTW; ++mi) {
                const int rb = wm + mi * 16 + (lane >> 2);
                const int cb = kk + (lane & 3);
                af[mi][0] = As[buf][rb    ][cb    ];
                af[mi][1] = As[buf][rb + 8][cb    ];
                af[mi][2] = As[buf][rb    ][cb + 4];
                af[mi][3] = As[buf][rb + 8][cb + 4];
            }
#pragma unroll
            for (int ni = 0; ni < 4; ++ni) {
                const int nb = wn + ni * 8 + (lane >> 2);
                bf[ni][0] = Bs[buf][kk +     (lane & 3)][nb];
                bf[ni][1] = Bs[buf][kk + 4 + (lane & 3)][nb];
            }
#pragma unroll
            for (int mi = 0; mi < MTW; ++mi)
#pragma unroll
                for (int ni = 0; ni < 4; ++ni)
                    mma_tf32(acc[mi][ni], af[mi][0], af[mi][1], af[mi][2], af[mi][3],
                             bf[ni][0], bf[ni][1]);
        }
    };

    const int T = K >> 5;
    stage(0, 0);
    __syncthreads();
    for (int t = 0; t < T; ++t) {
        if (t + 1 < T) stage((t + 1) << 5, (t + 1) & 1);
        mmatile(t & 1);
        __syncthreads();
    }

    // ---- epilogue ----
#pragma unroll
    for (int mi = 0; mi < MTW; ++mi) {
        const int r0 = m0 + wm + mi * 16 + (lane >> 2);
#pragma unroll
        for (int ni = 0; ni < 4; ++ni) {
            const int c0 = n0 + wn + ni * 8 + ((lane & 3) << 1);
            const float bv0 = HASBIAS ? bias[c0]     : 0.f;
            const float bv1 = HASBIAS ? bias[c0 + 1] : 0.f;
            float v0 = acc[mi][ni][0] + bv0;
            float v1 = acc[mi][ni][1] + bv1;
            float v2 = acc[mi][ni][2] + bv0;
            float v3 = acc[mi][ni][3] + bv1;
            if (MODE == 2) {
                if (n0 < AH_) {
#pragma unroll
                    for (int rr = 0; rr < 2; ++rr) {
                        const int row = r0 + rr * 8;
                        const int mq  = row >> 4;
                        const int bb  = row >> 13;
                        const int jj  = g_idx[row];
                        const float2 qa = *(const float2*)(g_QK + (size_t)mq * AH_ + c0);
                        const float2 ka = *(const float2*)(g_QK + (size_t)(M1 + bb * N_ + jj) * AH_ + c0);
                        float x0 = ((rr == 0) ? v0 : v2) + qa.x - ka.x;
                        float x1 = ((rr == 0) ? v1 : v3) + qa.y - ka.y;
                        x0 = fmaxf(x0, 0.f); x1 = fmaxf(x1, 0.f);
                        *(float2*)(C + (size_t)row * AH_ + c0) = make_float2(x0, x1);
                    }
                } else {
                    const int cp = c0 - AH_;
                    *(float2*)(C2 + (size_t)r0 * D_ + cp)       = make_float2(v0, v1);
                    *(float2*)(C2 + (size_t)(r0 + 8) * D_ + cp) = make_float2(v2, v3);
                }
            } else {
                *(float2*)(C + (size_t)r0 * N + c0)       = make_float2(v0, v1);
                *(float2*)(C + (size_t)(r0 + 8) * N + c0) = make_float2(v2, v3);
            }
        }
    }
}

// ---------------------------------------------------------------------------
// finalize: per-channel softmax over k + weighted sum (VG built inline).
// ---------------------------------------------------------------------------
__global__ void finalize_kernel(float* __restrict__ out) {
    __shared__ float ss[K_][D_ + 1];
    __shared__ float sv[K_][D_ + 1];
    const int m = blockIdx.x;
    const int b = m >> 9;
    const int i = m & (N_ - 1);
    const int tid = threadIdx.x;   // 128

    for (int t = tid; t < K_ * D_; t += blockDim.x) {
        const int kk = t >> 7, d = t & (D_ - 1);
        const int row = m * K_ + kk;
        const int j = g_idx[row];
        ss[kk][d] = g_SIM[(size_t)row * D_ + d];
        sv[kk][d] = g_qkv[(size_t)(b * N_ + j) * 384 + 256 + d] + g_PE[(size_t)row * D_ + d];
    }
    __syncthreads();

    const int d = tid;
    float mx = -3.4e38f;
#pragma unroll
    for (int kk = 0; kk < K_; ++kk) mx = fmaxf(mx, ss[kk][d]);
    float s = 0.f, agg = 0.f;
#pragma unroll
    for (int kk = 0; kk < K_; ++kk) {
        const float e = expf(ss[kk][d] - mx);
        s += e;
        agg = fmaf(e, sv[kk][d], agg);
    }
    out[(size_t)b * D_ * N_ + (size_t)d * N_ + i] = agg / s;
}

// ---------------------------------------------------------------------------
// Launch
// ---------------------------------------------------------------------------
extern "C" void kernel_launch(void* const* d_in, const int* in_sizes, int n_in,
                              void* d_out, int out_size) {
    const float* x    = (const float*)d_in[0];
    const float* pos  = (const float*)d_in[1];
    const float* wqkv = (const float*)d_in[2];
    const float* pw1  = (const float*)d_in[3];
    const float* pb1  = (const float*)d_in[4];
    const float* pw2  = (const float*)d_in[5];
    const float* pb2  = (const float*)d_in[6];
    const float* aw1  = (const float*)d_in[7];
    const float* ab1  = (const float*)d_in[8];
    const float* aw2  = (const float*)d_in[9];
    const float* ab2  = (const float*)d_in[10];
    float* out = (float*)d_out;

    void *pQKV = nullptr, *pHID = nullptr, *pQK = nullptr, *pWc = nullptr,
         *pBc = nullptr, *pPE = nullptr, *pA = nullptr, *pS = nullptr;
    cudaGetSymbolAddress(&pQKV, g_qkv);
    cudaGetSymbolAddress(&pHID, g_hid);
    cudaGetSymbolAddress(&pQK,  g_QK);
    cudaGetSymbolAddress(&pWc,  g_Wc);
    cudaGetSymbolAddress(&pBc,  g_bc);
    cudaGetSymbolAddress(&pPE,  g_PE);
    cudaGetSymbolAddress(&pA,   g_A);
    cudaGetSymbolAddress(&pS,   g_SIM);

    setup_kernel<<<M1, 128>>>(x, pos, wqkv, pw1, pb1);
    prep_w_kernel<<<547, 256>>>(pw2, pb2, aw1, ab1);
    // QA/KA = {q,k} @ aw1   (BM=64 -> 128 blocks)
    tc_gemm<2, 1, false><<<dim3(AH_ / 128, 2 * M1 / 64), 256>>>(
        (const float*)pQKV, aw1, nullptr, (float*)pQK, nullptr, 2 * M1, AH_, D_);
    // [A | PE] = hid @ Wc + bc  (A-cols get QA-KA gather + relu)
    tc_gemm<4, 2, true><<<dim3(NC_ / 128, M2 / 128), 256>>>(
        (const float*)pHID, (const float*)pWc, (const float*)pBc,
        (float*)pA, (float*)pPE, M2, NC_, PH_);
    // SIM = A @ aw2 + ab2   (BM=64 -> 256 blocks)
    tc_gemm<2, 0, true><<<dim3(1, M2 / 64), 256>>>(
        (const float*)pA, aw2, ab2, (float*)pS, nullptr, M2, D_, AH_);
    finalize_kernel<<<M1, 128>>>(out);
}

// round 10
// speedup vs baseline: 1.0753x; 1.0753x over previous
#include <cuda_runtime.h>
#include <math.h>
#include <stdint.h>

// ---------------------------------------------------------------------------
// Problem constants
// ---------------------------------------------------------------------------
namespace {
constexpr int B_  = 2;
constexpr int N_  = 512;
constexpr int D_  = 128;   // DIM
constexpr int PH_ = 64;    // POS_HID
constexpr int AH_ = 512;   // ATTN_HID
constexpr int K_  = 16;    // K_NEIGH
constexpr int M1  = B_ * N_;    // 1024
constexpr int M2  = M1 * K_;    // 16384
constexpr int NC_ = AH_ + D_;   // 640
}

// ---------------------------------------------------------------------------
// Scratch
// ---------------------------------------------------------------------------
__device__ float g_qkv[M1 * 3 * D_];
__device__ int   g_idx[M1 * K_];
__device__ float g_hid[M2 * PH_];
__device__ float g_QK [2 * M1 * AH_];   // rows 0..1023 = q@aw1, 1024..2047 = k@aw1
__device__ float g_Wc [PH_ * NC_];      // [pw2@aw1 | pw2]
__device__ float g_bc [NC_];            // [pb2@aw1 + ab1 | pb2]
__device__ float g_PE [M2 * D_];
__device__ float g_A  [M2 * AH_];
__device__ float g_SIM[M2 * D_];

// ---------------------------------------------------------------------------
// 1) setup: fused qkv + knn + hid (proven R8 version)
// ---------------------------------------------------------------------------
__global__ __launch_bounds__(128)
void setup_kernel(const float* __restrict__ x, const float* __restrict__ pos,
                  const float* __restrict__ wqkv,
                  const float* __restrict__ pw1, const float* __restrict__ pb1) {
    __shared__ float spx[N_], spy[N_], spz[N_];
    __shared__ float sxx[D_];
    __shared__ int   s_idx[K_];

    const int m = blockIdx.x;
    const int b = m >> 9;
    const int i = m & (N_ - 1);
    const int tid = threadIdx.x;

    for (int t = tid; t < N_; t += 128) {
        const float* p = pos + (size_t)(b * N_ + t) * 3;
        spx[t] = p[0]; spy[t] = p[1]; spz[t] = p[2];
    }
    sxx[tid] = x[b * D_ * N_ + tid * N_ + i];
    __syncthreads();

    if (tid < 32) {
        const int lane = tid;
        const float px = spx[i], py = spy[i], pz = spz[i];
        float d2[16];
#pragma unroll
        for (int t = 0; t < 16; ++t) {
            const int j = lane + 32 * t;
            const float dx = px - spx[j], dy = py - spy[j], dz = pz - spz[j];
            d2[t] = dx * dx + dy * dy + dz * dz;
        }
        unsigned taken = 0u;
        for (int it = 0; it < K_; ++it) {
            float best = 3.4e38f;
            int bt = -1;
#pragma unroll
            for (int t = 0; t < 16; ++t) {
                if (!((taken >> t) & 1u) && d2[t] < best) { best = d2[t]; bt = t; }
            }
            int bj = (bt < 0) ? 0x7fffffff : (lane + 32 * bt);
#pragma unroll
            for (int off = 16; off; off >>= 1) {
                const float ov = __shfl_xor_sync(0xffffffffu, best, off);
                const int   oj = __shfl_xor_sync(0xffffffffu, bj,   off);
                if (ov < best || (ov == best && oj < bj)) { best = ov; bj = oj; }
            }
            if ((bj & 31) == lane) taken |= 1u << (bj >> 5);
            if (lane == 0) { s_idx[it] = bj; g_idx[m * K_ + it] = bj; }
        }
    } else {
        const int t0 = tid - 32;
#pragma unroll
        for (int u = 0; u < 4; ++u) {
            const int c = t0 + u * 96;
            float a = 0.f;
#pragma unroll 8
            for (int d = 0; d < D_; ++d) a = fmaf(sxx[d], wqkv[d * 384 + c], a);
            g_qkv[(size_t)m * 384 + c] = a;
        }
    }
    __syncthreads();

    const int h = tid & 63;
    const float w0 = pw1[h], w1 = pw1[64 + h], w2 = pw1[128 + h], bb = pb1[h];
    const float px = spx[i], py = spy[i], pz = spz[i];
#pragma unroll
    for (int kp = 0; kp < 8; ++kp) {
        const int kk = kp * 2 + (tid >> 6);
        const int j = s_idx[kk];
        const float rx = px - spx[j], ry = py - spy[j], rz = pz - spz[j];
        float v = fmaf(rx, w0, fmaf(ry, w1, fmaf(rz, w2, bb)));
        g_hid[(size_t)(m * K_ + kk) * PH_ + h] = fmaxf(v, 0.f);
    }
}

// ---------------------------------------------------------------------------
// 2) prep_w (proven R8 split-K version)
// ---------------------------------------------------------------------------
__global__ __launch_bounds__(256)
void prep_w_kernel(const float* __restrict__ pw2, const float* __restrict__ pb2,
                   const float* __restrict__ aw1, const float* __restrict__ ab1) {
    const int blk = blockIdx.x;
    const int tid = threadIdx.x;
    if (blk < 512) {
        const int o = blk * 64 + (tid & 63);
        const int h = o >> 9, c = o & (AH_ - 1);
        const int sp = tid >> 6;
        float s = 0.f;
#pragma unroll
        for (int u = 0; u < 32; ++u) {
            const int d = sp * 32 + u;
            s = fmaf(pw2[h * D_ + d], aw1[d * AH_ + c], s);
        }
        __shared__ float red[4][64];
        red[sp][tid & 63] = s;
        __syncthreads();
        if (tid < 64)
            g_Wc[h * NC_ + c] = red[0][tid] + red[1][tid] + red[2][tid] + red[3][tid];
    } else if (blk < 544) {
        const int u = (blk - 512) * 256 + tid;
        const int h = u >> 7, d = u & (D_ - 1);
        g_Wc[h * NC_ + AH_ + d] = pw2[h * D_ + d];
    } else {
        const int c = (blk - 544) * 256 + tid;
        if (c < AH_) {
            float s0 = ab1[c], s1 = 0.f;
#pragma unroll 16
            for (int d = 0; d < D_; d += 2) {
                s0 = fmaf(pb2[d],     aw1[d * AH_ + c],       s0);
                s1 = fmaf(pb2[d + 1], aw1[(d + 1) * AH_ + c], s1);
            }
            g_bc[c] = s0 + s1;
        } else if (c < NC_) {
            g_bc[c] = pb2[c - AH_];
        }
    }
}

// ---------------------------------------------------------------------------
// Tensor-core tf32 GEMM (R3 layout). BM = 128 (MTW=4). DBUF toggles
// double-buffering (off for K=64 AP gemm -> half smem, 2x occupancy).
//   MODE 0 = plain            MODE 1 = A rows gathered from g_qkv (q then k)
//   MODE 2 = AP: cols <512 -> g_A with smem-QA + KA gather + relu;
//                cols >=512 -> g_PE
// ---------------------------------------------------------------------------
__device__ __forceinline__ uint32_t f2tf32(float f) {
    uint32_t u;
    asm("cvt.rna.tf32.f32 %0, %1;" : "=r"(u) : "f"(f));
    return u;
}

__device__ __forceinline__ void mma_tf32(float c[4],
                                         uint32_t a0, uint32_t a1, uint32_t a2, uint32_t a3,
                                         uint32_t b0, uint32_t b1) {
    asm volatile(
        "mma.sync.aligned.m16n8k8.row.col.f32.tf32.tf32.f32 "
        "{%0,%1,%2,%3}, {%4,%5,%6,%7}, {%8,%9}, {%0,%1,%2,%3};"
        : "+f"(c[0]), "+f"(c[1]), "+f"(c[2]), "+f"(c[3])
        : "r"(a0), "r"(a1), "r"(a2), "r"(a3), "r"(b0), "r"(b1));
}

template <int MODE, bool HASBIAS, bool DBUF>
__global__ __launch_bounds__(256)
void tc_gemm(const float* __restrict__ A, const float* __restrict__ W,
             const float* __restrict__ bias, float* __restrict__ C,
             float* __restrict__ C2, int M, int N, int K) {
    constexpr int NB = DBUF ? 2 : 1;
    __shared__ uint32_t As[NB][128][36];
    __shared__ uint32_t Bs[NB][32][136];
    __shared__ float    sQA[8][128 + 4];   // MODE 2 A-part only (adds 4.2KB)

    const int tid  = threadIdx.x;
    const int lane = tid & 31;
    const int warp = tid >> 5;
    const int wm = (warp >> 2) * 64;
    const int wn = (warp & 3) * 32;
    const int m0 = blockIdx.y * 128;
    const int n0 = blockIdx.x * 128;

    if (MODE == 2 && n0 < AH_) {
        const int q0 = m0 >> 4;   // first query of this block
#pragma unroll
        for (int t = 0; t < 4; ++t) {
            const int u = tid + t * 256;
            const int q = u >> 7, c = u & 127;
            sQA[q][c] = g_QK[(size_t)(q0 + q) * AH_ + n0 + c];
        }
    }

    float acc[4][4][4];
#pragma unroll
    for (int mi = 0; mi < 4; ++mi)
#pragma unroll
        for (int ni = 0; ni < 4; ++ni)
#pragma unroll
            for (int e = 0; e < 4; ++e) acc[mi][ni][e] = 0.f;

    auto stage = [&](int k0, int buf) {
#pragma unroll
        for (int t = 0; t < 4; ++t) {
            const int idx = tid + t * 256;
            const int r = idx >> 3, c = (idx & 7) << 2;
            float4 v;
            if (MODE == 1) {
                const int qrow = m0 + r;
                const size_t base = (size_t)(qrow & (M1 - 1)) * 384 + ((qrow >> 10) << 7);
                v = *(const float4*)(A + base + k0 + c);
            } else {
                v = *(const float4*)(A + (size_t)(m0 + r) * K + k0 + c);
            }
            As[buf][r][c + 0] = f2tf32(v.x); As[buf][r][c + 1] = f2tf32(v.y);
            As[buf][r][c + 2] = f2tf32(v.z); As[buf][r][c + 3] = f2tf32(v.w);
        }
#pragma unroll
        for (int t = 0; t < 4; ++t) {
            const int idx = tid + t * 256;
            const int kr = idx >> 5, nc = (idx & 31) << 2;
            const float4 v = *(const float4*)(W + (size_t)(k0 + kr) * N + n0 + nc);
            Bs[buf][kr][nc + 0] = f2tf32(v.x); Bs[buf][kr][nc + 1] = f2tf32(v.y);
            Bs[buf][kr][nc + 2] = f2tf32(v.z); Bs[buf][kr][nc + 3] = f2tf32(v.w);
        }
    };

    auto mmatile = [&](int buf) {
#pragma unroll
        for (int ks = 0; ks < 4; ++ks) {
            const int kk = ks * 8;
            uint32_t af[4][4], bf[4][2];
#pragma unroll
            for (int mi = 0; mi < 4; ++mi) {
                const int rb = wm + mi * 16 + (lane >> 2);
                const int cb = kk + (lane & 3);
                af[mi][0] = As[buf][rb    ][cb    ];
                af[mi][1] = As[buf][rb + 8][cb    ];
                af[mi][2] = As[buf][rb    ][cb + 4];
                af[mi][3] = As[buf][rb + 8][cb + 4];
            }
#pragma unroll
            for (int ni = 0; ni < 4; ++ni) {
                const int nb = wn + ni * 8 + (lane >> 2);
                bf[ni][0] = Bs[buf][kk +     (lane & 3)][nb];
                bf[ni][1] = Bs[buf][kk + 4 + (lane & 3)][nb];
            }
#pragma unroll
            for (int mi = 0; mi < 4; ++mi)
#pragma unroll
                for (int ni = 0; ni < 4; ++ni)
                    mma_tf32(acc[mi][ni], af[mi][0], af[mi][1], af[mi][2], af[mi][3],
                             bf[ni][0], bf[ni][1]);
        }
    };

    const int T = K >> 5;
    if (DBUF) {
        stage(0, 0);
        __syncthreads();
        for (int t = 0; t < T; ++t) {
            if (t + 1 < T) stage((t + 1) << 5, (t + 1) & 1);
            mmatile(t & 1);
            __syncthreads();
        }
    } else {
        for (int t = 0; t < T; ++t) {
            if (t > 0) __syncthreads();
            stage(t << 5, 0);
            __syncthreads();
            mmatile(0);
        }
    }

    // ---- epilogue ----
#pragma unroll
    for (int mi = 0; mi < 4; ++mi) {
        const int lr = wm + mi * 16 + (lane >> 2);   // local row 0..127
        const int r0 = m0 + lr;
        // MODE 2 hoists: same query for both row-halves of this mi tile
        int jj0 = 0, jj1 = 0, qA = 0, bb = 0;
        if (MODE == 2) {
            qA  = lr >> 4;
            bb  = r0 >> 13;
            jj0 = g_idx[r0];
            jj1 = g_idx[r0 + 8];
        }
#pragma unroll
        for (int ni = 0; ni < 4; ++ni) {
            const int cl = wn + ni * 8 + ((lane & 3) << 1);   // local col 0..127
            const int c0 = n0 + cl;
            const float bv0 = HASBIAS ? bias[c0]     : 0.f;
            const float bv1 = HASBIAS ? bias[c0 + 1] : 0.f;
            float v0 = acc[mi][ni][0] + bv0;
            float v1 = acc[mi][ni][1] + bv1;
            float v2 = acc[mi][ni][2] + bv0;
            float v3 = acc[mi][ni][3] + bv1;
            if (MODE == 2) {
                if (n0 < AH_) {
                    const float qa0 = sQA[qA][cl], qa1 = sQA[qA][cl + 1];
                    const float2 ka0 = *(const float2*)(g_QK + (size_t)(M1 + bb * N_ + jj0) * AH_ + c0);
                    const float2 ka1 = *(const float2*)(g_QK + (size_t)(M1 + bb * N_ + jj1) * AH_ + c0);
                    float x0 = fmaxf(v0 + qa0 - ka0.x, 0.f);
                    float x1 = fmaxf(v1 + qa1 - ka0.y, 0.f);
                    float x2 = fmaxf(v2 + qa0 - ka1.x, 0.f);
                    float x3 = fmaxf(v3 + qa1 - ka1.y, 0.f);
                    *(float2*)(C + (size_t)r0 * AH_ + c0)       = make_float2(x0, x1);
                    *(float2*)(C + (size_t)(r0 + 8) * AH_ + c0) = make_float2(x2, x3);
                } else {
                    const int cp = c0 - AH_;
                    *(float2*)(C2 + (size_t)r0 * D_ + cp)       = make_float2(v0, v1);
                    *(float2*)(C2 + (size_t)(r0 + 8) * D_ + cp) = make_float2(v2, v3);
                }
            } else {
                *(float2*)(C + (size_t)r0 * N + c0)       = make_float2(v0, v1);
                *(float2*)(C + (size_t)(r0 + 8) * N + c0) = make_float2(v2, v3);
            }
        }
    }
}

// ---------------------------------------------------------------------------
// finalize: per-channel softmax over k + weighted sum (VG built inline).
// ---------------------------------------------------------------------------
__global__ void finalize_kernel(float* __restrict__ out) {
    __shared__ float ss[K_][D_ + 1];
    __shared__ float sv[K_][D_ + 1];
    const int m = blockIdx.x;
    const int b = m >> 9;
    const int i = m & (N_ - 1);
    const int tid = threadIdx.x;   // 128

    for (int t = tid; t < K_ * D_; t += blockDim.x) {
        const int kk = t >> 7, d = t & (D_ - 1);
        const int row = m * K_ + kk;
        const int j = g_idx[row];
        ss[kk][d] = g_SIM[(size_t)row * D_ + d];
        sv[kk][d] = g_qkv[(size_t)(b * N_ + j) * 384 + 256 + d] + g_PE[(size_t)row * D_ + d];
    }
    __syncthreads();

    const int d = tid;
    float mx = -3.4e38f;
#pragma unroll
    for (int kk = 0; kk < K_; ++kk) mx = fmaxf(mx, ss[kk][d]);
    float s = 0.f, agg = 0.f;
#pragma unroll
    for (int kk = 0; kk < K_; ++kk) {
        const float e = expf(ss[kk][d] - mx);
        s += e;
        agg = fmaf(e, sv[kk][d], agg);
    }
    out[(size_t)b * D_ * N_ + (size_t)d * N_ + i] = agg / s;
}

// ---------------------------------------------------------------------------
// Launch
// ---------------------------------------------------------------------------
extern "C" void kernel_launch(void* const* d_in, const int* in_sizes, int n_in,
                              void* d_out, int out_size) {
    const float* x    = (const float*)d_in[0];
    const float* pos  = (const float*)d_in[1];
    const float* wqkv = (const float*)d_in[2];
    const float* pw1  = (const float*)d_in[3];
    const float* pb1  = (const float*)d_in[4];
    const float* pw2  = (const float*)d_in[5];
    const float* pb2  = (const float*)d_in[6];
    const float* aw1  = (const float*)d_in[7];
    const float* ab1  = (const float*)d_in[8];
    const float* aw2  = (const float*)d_in[9];
    const float* ab2  = (const float*)d_in[10];
    float* out = (float*)d_out;

    void *pQKV = nullptr, *pHID = nullptr, *pQK = nullptr, *pWc = nullptr,
         *pBc = nullptr, *pPE = nullptr, *pA = nullptr, *pS = nullptr;
    cudaGetSymbolAddress(&pQKV, g_qkv);
    cudaGetSymbolAddress(&pHID, g_hid);
    cudaGetSymbolAddress(&pQK,  g_QK);
    cudaGetSymbolAddress(&pWc,  g_Wc);
    cudaGetSymbolAddress(&pBc,  g_bc);
    cudaGetSymbolAddress(&pPE,  g_PE);
    cudaGetSymbolAddress(&pA,   g_A);
    cudaGetSymbolAddress(&pS,   g_SIM);

    setup_kernel<<<M1, 128>>>(x, pos, wqkv, pw1, pb1);
    prep_w_kernel<<<547, 256>>>(pw2, pb2, aw1, ab1);
    // QA/KA = {q,k} @ aw1   (BM=128)
    tc_gemm<1, false, true><<<dim3(AH_ / 128, 2 * M1 / 128), 256>>>(
        (const float*)pQKV, aw1, nullptr, (float*)pQK, nullptr, 2 * M1, AH_, D_);
    // [A | PE] = hid @ Wc + bc  (single-buffer; smem QA; KA gather + relu)
    tc_gemm<2, true, false><<<dim3(NC_ / 128, M2 / 128), 256>>>(
        (const float*)pHID, (const float*)pWc, (const float*)pBc,
        (float*)pA, (float*)pPE, M2, NC_, PH_);
    // SIM = A @ aw2 + ab2   (BM=128)
    tc_gemm<0, true, true><<<dim3(1, M2 / 128), 256>>>(
        (const float*)pA, aw2, ab2, (float*)pS, nullptr, M2, D_, AH_);
    finalize_kernel<<<M1, 128>>>(out);
}

// round 13
// speedup vs baseline: 1.5055x; 1.4002x over previous
#include <cuda_runtime.h>
#include <math.h>
#include <stdint.h>

// ---------------------------------------------------------------------------
// Problem constants
// ---------------------------------------------------------------------------
namespace {
constexpr int B_  = 2;
constexpr int N_  = 512;
constexpr int D_  = 128;
constexpr int PH_ = 64;
constexpr int AH_ = 512;
constexpr int K_  = 16;
constexpr int M1  = B_ * N_;    // 1024
constexpr int M2  = M1 * K_;    // 16384
constexpr int NC_ = AH_ + D_;   // 640
}

// ---------------------------------------------------------------------------
// Scratch
// ---------------------------------------------------------------------------
__device__ float g_qkv[M1 * 3 * D_];
__device__ int   g_idx[M1 * K_];
__device__ float g_hid[M2 * PH_];
__device__ float g_QK [2 * M1 * AH_];   // rows 0..1023 = q@aw1, 1024..2047 = k@aw1
__device__ float g_Wc [PH_ * NC_];      // [pw2@aw1 | pw2]
__device__ float g_bc [NC_];            // [pb2@aw1 + ab1 | pb2]

__device__ __forceinline__ uint32_t f2tf32(float f) {
    uint32_t u;
    asm("cvt.rna.tf32.f32 %0, %1;" : "=r"(u) : "f"(f));
    return u;
}

__device__ __forceinline__ void mma_tf32(float c[4],
                                         uint32_t a0, uint32_t a1, uint32_t a2, uint32_t a3,
                                         uint32_t b0, uint32_t b1) {
    asm volatile(
        "mma.sync.aligned.m16n8k8.row.col.f32.tf32.tf32.f32 "
        "{%0,%1,%2,%3}, {%4,%5,%6,%7}, {%8,%9}, {%0,%1,%2,%3};"
        : "+f"(c[0]), "+f"(c[1]), "+f"(c[2]), "+f"(c[3])
        : "r"(a0), "r"(a1), "r"(a2), "r"(a3), "r"(b0), "r"(b1));
}

// ---------------------------------------------------------------------------
// 1) setup: fused qkv + knn + hid (proven)
// ---------------------------------------------------------------------------
__global__ __launch_bounds__(128)
void setup_kernel(const float* __restrict__ x, const float* __restrict__ pos,
                  const float* __restrict__ wqkv,
                  const float* __restrict__ pw1, const float* __restrict__ pb1) {
    __shared__ float spx[N_], spy[N_], spz[N_];
    __shared__ float sxx[D_];
    __shared__ int   s_idx[K_];

    const int m = blockIdx.x;
    const int b = m >> 9;
    const int i = m & (N_ - 1);
    const int tid = threadIdx.x;

    for (int t = tid; t < N_; t += 128) {
        const float* p = pos + (size_t)(b * N_ + t) * 3;
        spx[t] = p[0]; spy[t] = p[1]; spz[t] = p[2];
    }
    sxx[tid] = x[b * D_ * N_ + tid * N_ + i];
    __syncthreads();

    if (tid < 32) {
        const int lane = tid;
        const float px = spx[i], py = spy[i], pz = spz[i];
        float d2[16];
#pragma unroll
        for (int t = 0; t < 16; ++t) {
            const int j = lane + 32 * t;
            const float dx = px - spx[j], dy = py - spy[j], dz = pz - spz[j];
            d2[t] = dx * dx + dy * dy + dz * dz;
        }
        unsigned taken = 0u;
        for (int it = 0; it < K_; ++it) {
            float best = 3.4e38f;
            int bt = -1;
#pragma unroll
            for (int t = 0; t < 16; ++t) {
                if (!((taken >> t) & 1u) && d2[t] < best) { best = d2[t]; bt = t; }
            }
            int bj = (bt < 0) ? 0x7fffffff : (lane + 32 * bt);
#pragma unroll
            for (int off = 16; off; off >>= 1) {
                const float ov = __shfl_xor_sync(0xffffffffu, best, off);
                const int   oj = __shfl_xor_sync(0xffffffffu, bj,   off);
                if (ov < best || (ov == best && oj < bj)) { best = ov; bj = oj; }
            }
            if ((bj & 31) == lane) taken |= 1u << (bj >> 5);
            if (lane == 0) { s_idx[it] = bj; g_idx[m * K_ + it] = bj; }
        }
    } else {
        const int t0 = tid - 32;
#pragma unroll
        for (int u = 0; u < 4; ++u) {
            const int c = t0 + u * 96;
            float a = 0.f;
#pragma unroll 8
            for (int d = 0; d < D_; ++d) a = fmaf(sxx[d], wqkv[d * 384 + c], a);
            g_qkv[(size_t)m * 384 + c] = a;
        }
    }
    __syncthreads();

    const int h = tid & 63;
    const float w0 = pw1[h], w1 = pw1[64 + h], w2 = pw1[128 + h], bb = pb1[h];
    const float px = spx[i], py = spy[i], pz = spz[i];
#pragma unroll
    for (int kp = 0; kp < 8; ++kp) {
        const int kk = kp * 2 + (tid >> 6);
        const int j = s_idx[kk];
        const float rx = px - spx[j], ry = py - spy[j], rz = pz - spz[j];
        float v = fmaf(rx, w0, fmaf(ry, w1, fmaf(rz, w2, bb)));
        g_hid[(size_t)(m * K_ + kk) * PH_ + h] = fmaxf(v, 0.f);
    }
}

// ---------------------------------------------------------------------------
// 2) prep_w (proven split-K version)
// ---------------------------------------------------------------------------
__global__ __launch_bounds__(256)
void prep_w_kernel(const float* __restrict__ pw2, const float* __restrict__ pb2,
                   const float* __restrict__ aw1, const float* __restrict__ ab1) {
    const int blk = blockIdx.x;
    const int tid = threadIdx.x;
    if (blk < 512) {
        const int o = blk * 64 + (tid & 63);
        const int h = o >> 9, c = o & (AH_ - 1);
        const int sp = tid >> 6;
        float s = 0.f;
#pragma unroll
        for (int u = 0; u < 32; ++u) {
            const int d = sp * 32 + u;
            s = fmaf(pw2[h * D_ + d], aw1[d * AH_ + c], s);
        }
        __shared__ float red[4][64];
        red[sp][tid & 63] = s;
        __syncthreads();
        if (tid < 64)
            g_Wc[h * NC_ + c] = red[0][tid] + red[1][tid] + red[2][tid] + red[3][tid];
    } else if (blk < 544) {
        const int u = (blk - 512) * 256 + tid;
        const int h = u >> 7, d = u & (D_ - 1);
        g_Wc[h * NC_ + AH_ + d] = pw2[h * D_ + d];
    } else {
        const int c = (blk - 544) * 256 + tid;
        if (c < AH_) {
            float s0 = ab1[c], s1 = 0.f;
#pragma unroll 16
            for (int d = 0; d < D_; d += 2) {
                s0 = fmaf(pb2[d],     aw1[d * AH_ + c],       s0);
                s1 = fmaf(pb2[d + 1], aw1[(d + 1) * AH_ + c], s1);
            }
            g_bc[c] = s0 + s1;
        } else if (c < NC_) {
            g_bc[c] = pb2[c - AH_];
        }
    }
}

// ---------------------------------------------------------------------------
// 3) QK gemm: QA/KA = {q,k} @ aw1 (proven, double-buffered)
// ---------------------------------------------------------------------------
__global__ __launch_bounds__(256)
void qk_gemm(const float* __restrict__ W, float* __restrict__ C) {
    __shared__ uint32_t As[2][128][36];
    __shared__ uint32_t Bs[2][32][136];

    const int tid  = threadIdx.x;
    const int lane = tid & 31;
    const int warp = tid >> 5;
    const int wm = (warp >> 2) * 64;
    const int wn = (warp & 3) * 32;
    const int m0 = blockIdx.y * 128;
    const int n0 = blockIdx.x * 128;

    float acc[4][4][4];
#pragma unroll
    for (int mi = 0; mi < 4; ++mi)
#pragma unroll
        for (int ni = 0; ni < 4; ++ni)
#pragma unroll
            for (int e = 0; e < 4; ++e) acc[mi][ni][e] = 0.f;

    auto stage = [&](int k0, int buf) {
#pragma unroll
        for (int t = 0; t < 4; ++t) {
            const int idx = tid + t * 256;
            const int r = idx >> 3, c = (idx & 7) << 2;
            const int qrow = m0 + r;
            const size_t base = (size_t)(qrow & (M1 - 1)) * 384 + ((qrow >> 10) << 7);
            const float4 v = *(const float4*)(g_qkv + base + k0 + c);
            As[buf][r][c + 0] = f2tf32(v.x); As[buf][r][c + 1] = f2tf32(v.y);
            As[buf][r][c + 2] = f2tf32(v.z); As[buf][r][c + 3] = f2tf32(v.w);
        }
#pragma unroll
        for (int t = 0; t < 4; ++t) {
            const int idx = tid + t * 256;
            const int kr = idx >> 5, nc = (idx & 31) << 2;
            const float4 v = *(const float4*)(W + (size_t)(k0 + kr) * AH_ + n0 + nc);
            Bs[buf][kr][nc + 0] = f2tf32(v.x); Bs[buf][kr][nc + 1] = f2tf32(v.y);
            Bs[buf][kr][nc + 2] = f2tf32(v.z); Bs[buf][kr][nc + 3] = f2tf32(v.w);
        }
    };

    auto mmatile = [&](int buf) {
#pragma unroll
        for (int ks = 0; ks < 4; ++ks) {
            const int kk = ks * 8;
            uint32_t af[4][4], bf[4][2];
#pragma unroll
            for (int mi = 0; mi < 4; ++mi) {
                const int rb = wm + mi * 16 + (lane >> 2);
                const int cb = kk + (lane & 3);
                af[mi][0] = As[buf][rb    ][cb    ];
                af[mi][1] = As[buf][rb + 8][cb    ];
                af[mi][2] = As[buf][rb    ][cb + 4];
                af[mi][3] = As[buf][rb + 8][cb + 4];
            }
#pragma unroll
            for (int ni = 0; ni < 4; ++ni) {
                const int nb = wn + ni * 8 + (lane >> 2);
                bf[ni][0] = Bs[buf][kk +     (lane & 3)][nb];
                bf[ni][1] = Bs[buf][kk + 4 + (lane & 3)][nb];
            }
#pragma unroll
            for (int mi = 0; mi < 4; ++mi)
#pragma unroll
                for (int ni = 0; ni < 4; ++ni)
                    mma_tf32(acc[mi][ni], af[mi][0], af[mi][1], af[mi][2], af[mi][3],
                             bf[ni][0], bf[ni][1]);
        }
    };

    stage(0, 0);
    __syncthreads();
#pragma unroll
    for (int t = 0; t < 4; ++t) {
        if (t < 3) stage((t + 1) << 5, (t + 1) & 1);
        mmatile(t & 1);
        __syncthreads();
    }

#pragma unroll
    for (int mi = 0; mi < 4; ++mi) {
        const int r0 = m0 + wm + mi * 16 + (lane >> 2);
#pragma unroll
        for (int ni = 0; ni < 4; ++ni) {
            const int c0 = n0 + wn + ni * 8 + ((lane & 3) << 1);
            *(float2*)(C + (size_t)r0 * AH_ + c0)       = make_float2(acc[mi][ni][0], acc[mi][ni][1]);
            *(float2*)(C + (size_t)(r0 + 8) * AH_ + c0) = make_float2(acc[mi][ni][2], acc[mi][ni][3]);
        }
    }
}

// ---------------------------------------------------------------------------
// 4) MEGA-FUSED: per-block 64 rows (4 queries). A/SIM/PE live only in smem.
// ---------------------------------------------------------------------------
constexpr int SM_HID = 0;
constexpr int SM_BS  = 17408;
constexpr int SM_ASA = 34816;
constexpr int SM_SIM = 68608;
constexpr int SM_QA  = 102400;
constexpr int SM_JJ  = 104512;
constexpr int SM_TOT = 104768;

__global__ __launch_bounds__(256)
void fused_kernel(const float* __restrict__ aw2, float* __restrict__ out) {
    extern __shared__ char smem[];
    uint32_t* sHid = (uint32_t*)(smem + SM_HID);
    uint32_t* sBs  = (uint32_t*)(smem + SM_BS);
    uint32_t* sAsA = (uint32_t*)(smem + SM_ASA);
    float*    sPE  = (float*)   (smem + SM_ASA);
    float*    sSIM = (float*)   (smem + SM_SIM);
    float*    sQA  = (float*)   (smem + SM_QA);
    int*      sJJ  = (int*)     (smem + SM_JJ);

    const int tid  = threadIdx.x;
    const int lane = tid & 31;
    const int warp = tid >> 5;
    const int wm = (warp >> 2) * 32;   // 2x4 warp grid, warp tile 32x32
    const int wn = (warp & 3) * 32;
    const int m0 = blockIdx.x * 64;
    const int b  = m0 >> 13;
    const int q0 = m0 >> 4;

    // ---- stage hid (64x64 tf32) + neighbor indices ----
#pragma unroll
    for (int t = 0; t < 4; ++t) {
        const int idx = tid + t * 256;
        const int r = idx >> 4, c = (idx & 15) << 2;
        const float4 v = *(const float4*)(g_hid + (size_t)(m0 + r) * PH_ + c);
        sHid[r * 68 + c + 0] = f2tf32(v.x); sHid[r * 68 + c + 1] = f2tf32(v.y);
        sHid[r * 68 + c + 2] = f2tf32(v.z); sHid[r * 68 + c + 3] = f2tf32(v.w);
    }
    if (tid < 64) sJJ[tid] = g_idx[m0 + tid];
    __syncthreads();

    float accS[2][4][4];
#pragma unroll
    for (int mi = 0; mi < 2; ++mi)
#pragma unroll
        for (int ni = 0; ni < 4; ++ni)
#pragma unroll
            for (int e = 0; e < 4; ++e) accS[mi][ni][e] = 0.f;

    // ================= chunks over AH =================
    for (int ch = 0; ch < 4; ++ch) {
        const int n0c = ch * 128;

        // QA for these 4 queries, this chunk
#pragma unroll
        for (int t = 0; t < 2; ++t) {
            const int u = tid + t * 256;
            const int q = u >> 7, c = u & 127;
            sQA[q * 132 + c] = g_QK[(size_t)(q0 + q) * AH_ + n0c + c];
        }

        float accA[2][4][4];
#pragma unroll
        for (int mi = 0; mi < 2; ++mi)
#pragma unroll
            for (int ni = 0; ni < 4; ++ni)
#pragma unroll
                for (int e = 0; e < 4; ++e) accA[mi][ni][e] = 0.f;

        // ---- Ablk = hid @ Wc[:, n0c..n0c+128) ----
#pragma unroll
        for (int t = 0; t < 2; ++t) {
            __syncthreads();
            // stage Wc k-rows 32t..32t+31 x 128 cols  (FIX: full 4-pass stage)
#pragma unroll
            for (int u = 0; u < 4; ++u) {
                const int idx = tid + u * 256;
                const int kr = idx >> 5, nc = (idx & 31) << 2;
                const float4 v = *(const float4*)(g_Wc + (size_t)(32 * t + kr) * NC_ + n0c + nc);
                sBs[kr * 136 + nc + 0] = f2tf32(v.x); sBs[kr * 136 + nc + 1] = f2tf32(v.y);
                sBs[kr * 136 + nc + 2] = f2tf32(v.z); sBs[kr * 136 + nc + 3] = f2tf32(v.w);
            }
            __syncthreads();
#pragma unroll
            for (int ks = 0; ks < 4; ++ks) {
                const int kk = ks * 8;
                uint32_t af[2][4], bf[4][2];
#pragma unroll
                for (int mi = 0; mi < 2; ++mi) {
                    const int rb = wm + mi * 16 + (lane >> 2);
                    const int cb = 32 * t + kk + (lane & 3);
                    af[mi][0] = sHid[rb * 68 + cb];
                    af[mi][1] = sHid[(rb + 8) * 68 + cb];
                    af[mi][2] = sHid[rb * 68 + cb + 4];
                    af[mi][3] = sHid[(rb + 8) * 68 + cb + 4];
                }
#pragma unroll
                for (int ni = 0; ni < 4; ++ni) {
                    const int nb = wn + ni * 8 + (lane >> 2);
                    bf[ni][0] = sBs[(kk +     (lane & 3)) * 136 + nb];
                    bf[ni][1] = sBs[(kk + 4 + (lane & 3)) * 136 + nb];
                }
#pragma unroll
                for (int mi = 0; mi < 2; ++mi)
#pragma unroll
                    for (int ni = 0; ni < 4; ++ni)
                        mma_tf32(accA[mi][ni], af[mi][0], af[mi][1], af[mi][2], af[mi][3],
                                 bf[ni][0], bf[ni][1]);
            }
        }
        __syncthreads();   // prior chunk's SIM mma done reading sAsA

        // ---- epilogue: + bc + QA - KA, relu -> sAsA (tf32) ----
#pragma unroll
        for (int mi = 0; mi < 2; ++mi) {
            const int lr = wm + mi * 16 + (lane >> 2);
            const int q  = lr >> 4;
            const int j0 = sJJ[lr], j1 = sJJ[lr + 8];
            const size_t ka0b = (size_t)(M1 + b * N_ + j0) * AH_ + n0c;
            const size_t ka1b = (size_t)(M1 + b * N_ + j1) * AH_ + n0c;
#pragma unroll
            for (int ni = 0; ni < 4; ++ni) {
                const int cl = wn + ni * 8 + ((lane & 3) << 1);
                const float bc0 = g_bc[n0c + cl], bc1 = g_bc[n0c + cl + 1];
                const float qa0 = sQA[q * 132 + cl], qa1 = sQA[q * 132 + cl + 1];
                const float2 ka0 = *(const float2*)(g_QK + ka0b + cl);
                const float2 ka1 = *(const float2*)(g_QK + ka1b + cl);
                const float x0 = fmaxf(accA[mi][ni][0] + bc0 + qa0 - ka0.x, 0.f);
                const float x1 = fmaxf(accA[mi][ni][1] + bc1 + qa1 - ka0.y, 0.f);
                const float x2 = fmaxf(accA[mi][ni][2] + bc0 + qa0 - ka1.x, 0.f);
                const float x3 = fmaxf(accA[mi][ni][3] + bc1 + qa1 - ka1.y, 0.f);
                sAsA[lr * 132 + cl]           = f2tf32(x0);
                sAsA[lr * 132 + cl + 1]       = f2tf32(x1);
                sAsA[(lr + 8) * 132 + cl]     = f2tf32(x2);
                sAsA[(lr + 8) * 132 + cl + 1] = f2tf32(x3);
            }
        }

        // ---- SIM += Ablk @ aw2[n0c..n0c+128, :] ----
#pragma unroll
        for (int ts = 0; ts < 4; ++ts) {
            __syncthreads();
            // stage aw2 k-rows n0c+32ts..+31 x 128 cols  (FIX: full 4-pass stage)
#pragma unroll
            for (int u = 0; u < 4; ++u) {
                const int idx = tid + u * 256;
                const int kr = idx >> 5, nc = (idx & 31) << 2;
                const float4 v = *(const float4*)(aw2 + (size_t)(n0c + ts * 32 + kr) * D_ + nc);
                sBs[kr * 136 + nc + 0] = f2tf32(v.x); sBs[kr * 136 + nc + 1] = f2tf32(v.y);
                sBs[kr * 136 + nc + 2] = f2tf32(v.z); sBs[kr * 136 + nc + 3] = f2tf32(v.w);
            }
            __syncthreads();
#pragma unroll
            for (int ks = 0; ks < 4; ++ks) {
                const int kk = ks * 8;
                uint32_t af[2][4], bf[4][2];
#pragma unroll
                for (int mi = 0; mi < 2; ++mi) {
                    const int rb = wm + mi * 16 + (lane >> 2);
                    const int cb = ts * 32 + kk + (lane & 3);
                    af[mi][0] = sAsA[rb * 132 + cb];
                    af[mi][1] = sAsA[(rb + 8) * 132 + cb];
                    af[mi][2] = sAsA[rb * 132 + cb + 4];
                    af[mi][3] = sAsA[(rb + 8) * 132 + cb + 4];
                }
#pragma unroll
                for (int ni = 0; ni < 4; ++ni) {
                    const int nb = wn + ni * 8 + (lane >> 2);
                    bf[ni][0] = sBs[(kk +     (lane & 3)) * 136 + nb];
                    bf[ni][1] = sBs[(kk + 4 + (lane & 3)) * 136 + nb];
                }
#pragma unroll
                for (int mi = 0; mi < 2; ++mi)
#pragma unroll
                    for (int ni = 0; ni < 4; ++ni)
                        mma_tf32(accS[mi][ni], af[mi][0], af[mi][1], af[mi][2], af[mi][3],
                                 bf[ni][0], bf[ni][1]);
            }
        }
    }

    // ---- dump SIM to smem (ab2 omitted: constant over softmax axis) ----
#pragma unroll
    for (int mi = 0; mi < 2; ++mi) {
        const int lr = wm + mi * 16 + (lane >> 2);
#pragma unroll
        for (int ni = 0; ni < 4; ++ni) {
            const int cl = wn + ni * 8 + ((lane & 3) << 1);
            sSIM[lr * 132 + cl]           = accS[mi][ni][0];
            sSIM[lr * 132 + cl + 1]       = accS[mi][ni][1];
            sSIM[(lr + 8) * 132 + cl]     = accS[mi][ni][2];
            sSIM[(lr + 8) * 132 + cl + 1] = accS[mi][ni][3];
        }
    }
    __syncthreads();

    // ---- PE = hid @ Wc[:,512:640) + bc -> sPE (reuses sAsA region) ----
    {
        float accP[2][4][4];
#pragma unroll
        for (int mi = 0; mi < 2; ++mi)
#pragma unroll
            for (int ni = 0; ni < 4; ++ni)
#pragma unroll
                for (int e = 0; e < 4; ++e) accP[mi][ni][e] = 0.f;
#pragma unroll
        for (int t = 0; t < 2; ++t) {
            __syncthreads();
            // stage Wc PE-cols k-rows 32t..32t+31 (FIX: full 4-pass stage)
#pragma unroll
            for (int u = 0; u < 4; ++u) {
                const int idx = tid + u * 256;
                const int kr = idx >> 5, nc = (idx & 31) << 2;
                const float4 v = *(const float4*)(g_Wc + (size_t)(32 * t + kr) * NC_ + AH_ + nc);
                sBs[kr * 136 + nc + 0] = f2tf32(v.x); sBs[kr * 136 + nc + 1] = f2tf32(v.y);
                sBs[kr * 136 + nc + 2] = f2tf32(v.z); sBs[kr * 136 + nc + 3] = f2tf32(v.w);
            }
            __syncthreads();
#pragma unroll
            for (int ks = 0; ks < 4; ++ks) {
                const int kk = ks * 8;
                uint32_t af[2][4], bf[4][2];
#pragma unroll
                for (int mi = 0; mi < 2; ++mi) {
                    const int rb = wm + mi * 16 + (lane >> 2);
                    const int cb = 32 * t + kk + (lane & 3);
                    af[mi][0] = sHid[rb * 68 + cb];
                    af[mi][1] = sHid[(rb + 8) * 68 + cb];
                    af[mi][2] = sHid[rb * 68 + cb + 4];
                    af[mi][3] = sHid[(rb + 8) * 68 + cb + 4];
                }
#pragma unroll
                for (int ni = 0; ni < 4; ++ni) {
                    const int nb = wn + ni * 8 + (lane >> 2);
                    bf[ni][0] = sBs[(kk +     (lane & 3)) * 136 + nb];
                    bf[ni][1] = sBs[(kk + 4 + (lane & 3)) * 136 + nb];
                }
#pragma unroll
                for (int mi = 0; mi < 2; ++mi)
#pragma unroll
                    for (int ni = 0; ni < 4; ++ni)
                        mma_tf32(accP[mi][ni], af[mi][0], af[mi][1], af[mi][2], af[mi][3],
                                 bf[ni][0], bf[ni][1]);
            }
        }
        __syncthreads();   // before overwriting sAsA region as sPE
#pragma unroll
        for (int mi = 0; mi < 2; ++mi) {
            const int lr = wm + mi * 16 + (lane >> 2);
#pragma unroll
            for (int ni = 0; ni < 4; ++ni) {
                const int cl = wn + ni * 8 + ((lane & 3) << 1);
                sPE[lr * 132 + cl]           = accP[mi][ni][0] + g_bc[AH_ + cl];
                sPE[lr * 132 + cl + 1]       = accP[mi][ni][1] + g_bc[AH_ + cl + 1];
                sPE[(lr + 8) * 132 + cl]     = accP[mi][ni][2] + g_bc[AH_ + cl];
                sPE[(lr + 8) * 132 + cl + 1] = accP[mi][ni][3] + g_bc[AH_ + cl + 1];
            }
        }
    }
    __syncthreads();

    // ---- finalize: softmax over 16 neighbors + v gather, transposed store ----
#pragma unroll
    for (int u = 0; u < 2; ++u) {
        const int item = tid + u * 256;        // 512 = 4 queries x 128 ch
        const int q = item >> 7, c = item & 127;
        const int r0 = q * 16;
        float mx = -3.4e38f;
#pragma unroll
        for (int kk = 0; kk < K_; ++kk) mx = fmaxf(mx, sSIM[(r0 + kk) * 132 + c]);
        float s = 0.f, agg = 0.f;
#pragma unroll
        for (int kk = 0; kk < K_; ++kk) {
            const float e = expf(sSIM[(r0 + kk) * 132 + c] - mx);
            s += e;
            const int j = sJJ[r0 + kk];
            const float vg = g_qkv[(size_t)(b * N_ + j) * 384 + 256 + c] + sPE[(r0 + kk) * 132 + c];
            agg = fmaf(e, vg, agg);
        }
        const int ig = (q0 + q) & (N_ - 1);
        out[(size_t)b * D_ * N_ + (size_t)c * N_ + ig] = agg / s;
    }
}

// ---------------------------------------------------------------------------
// Launch
// ---------------------------------------------------------------------------
extern "C" void kernel_launch(void* const* d_in, const int* in_sizes, int n_in,
                              void* d_out, int out_size) {
    const float* x    = (const float*)d_in[0];
    const float* pos  = (const float*)d_in[1];
    const float* wqkv = (const float*)d_in[2];
    const float* pw1  = (const float*)d_in[3];
    const float* pb1  = (const float*)d_in[4];
    const float* pw2  = (const float*)d_in[5];
    const float* pb2  = (const float*)d_in[6];
    const float* aw1  = (const float*)d_in[7];
    const float* ab1  = (const float*)d_in[8];
    const float* aw2  = (const float*)d_in[9];
    float* out = (float*)d_out;

    void* pQK = nullptr;
    cudaGetSymbolAddress(&pQK, g_QK);

    static bool attr_set = false;
    if (!attr_set) {
        cudaFuncSetAttribute(fused_kernel, cudaFuncAttributeMaxDynamicSharedMemorySize, SM_TOT);
        attr_set = true;
    }

    setup_kernel<<<M1, 128>>>(x, pos, wqkv, pw1, pb1);
    prep_w_kernel<<<547, 256>>>(pw2, pb2, aw1, ab1);
    qk_gemm<<<dim3(AH_ / 128, 2 * M1 / 128), 256>>>(aw1, (float*)pQK);
    fused_kernel<<<M2 / 64, 256, SM_TOT>>>(aw2, out);
}